// round 14
// baseline (speedup 1.0000x reference)
#include <cuda_runtime.h>
#include <cuda_bf16.h>
#include <float.h>
#include <cstdint>

// Problem constants
#define BB   8
#define NN   8192
#define MM   4096
#define CC   128
#define KNN  16
#define CO   256
#define CI1  131
#define ROWS (BB*MM*KNN)  // 524288
#define QTOT (BB*MM)      // 32768
#define NEWPOS_ELEMS (QTOT*3)
#define NTILE (ROWS/128)        // 4096
#define NWORK (2*NTILE)         // 8192

// ---------------- static scratch (allocation-free rule) ----------------
__device__ float g_P [ (size_t)BB*NN*CO ];       // 64 MB  points @ W1p^T (L2-resident)
__device__ float g_hmax[ (size_t)QTOT*CO ];      // 32 MB
__device__ float g_hmin[ (size_t)QTOT*CO ];      // 32 MB
__device__ int   g_knn[ ROWS ];                  // 2 MB
__device__ __nv_bfloat16 g_Bhi[CO*CO];
__device__ __nv_bfloat16 g_Blo[CO*CO];
__device__ float g_sum1[CO], g_sumsq1[CO], g_sum2[CO], g_sumsq2[CO];

// ========== launch 0: fused kNN (blocks 0..127) + gemm_p/W2split (128..1151) ==
__global__ __launch_bounds__(256)
void knn_gemmp_kernel(const float* __restrict__ pos, const int* __restrict__ idx,
                      float* __restrict__ out_newpos,
                      const float* __restrict__ points,
                      const float* __restrict__ W1, const float* __restrict__ W2)
{
    __shared__ char smem_u[32768];

    if (blockIdx.x < 128) {
        // ---------------- kNN part ----------------
        if (blockIdx.x == 0 && threadIdx.x < CO) {
            int tt = threadIdx.x;
            g_sum1[tt] = 0.f;  g_sumsq1[tt] = 0.f;
            g_sum2[tt] = 0.f;  g_sumsq2[tt] = 0.f;
        }
        float4* sp = reinterpret_cast<float4*>(smem_u);
        const int q = blockIdx.x * 256 + threadIdx.x;
        const int b = q >> 12;
        const float* pb = pos + (size_t)b * NN * 3;

        const int nq = idx[q];
        const float qx = pb[nq*3+0], qy = pb[nq*3+1], qz = pb[nq*3+2];
        out_newpos[q*3+0] = qx; out_newpos[q*3+1] = qy; out_newpos[q*3+2] = qz;
        const float qn = qx*qx + qy*qy + qz*qz;

        float dist[KNN]; int ind[KNN];
#pragma unroll
        for (int j = 0; j < KNN; j++) { dist[j] = FLT_MAX; ind[j] = 0x7fffffff; }

        for (int c0 = 0; c0 < NN; c0 += 2048) {
            __syncthreads();
            for (int i = threadIdx.x; i < 2048; i += 256) {
                float x = pb[(c0+i)*3+0], y = pb[(c0+i)*3+1], z = pb[(c0+i)*3+2];
                sp[i] = make_float4(x, y, z, x*x + y*y + z*z);
            }
            __syncthreads();
#pragma unroll 4
            for (int i = 0; i < 2048; i++) {
                float4 p = sp[i];
                float qp = qx*p.x + qy*p.y + qz*p.z;
                float d  = qn - 2.0f*qp + p.w;
                if (d < dist[0]) {
                    const int nidx = c0 + i;
                    bool prev = true;
#pragma unroll
                    for (int j = 0; j < KNN-1; j++) {
                        bool nxt = d < dist[j+1];
                        float dj = nxt ? dist[j+1] : (prev ? d    : dist[j]);
                        int   ij = nxt ? ind[j+1]  : (prev ? nidx : ind[j]);
                        dist[j] = dj; ind[j] = ij;
                        prev = nxt;
                    }
                    if (prev) { dist[KNN-1] = d; ind[KNN-1] = nidx; }
                }
            }
        }
#pragma unroll
        for (int j = 0; j < KNN; j++) g_knn[q*KNN + j] = ind[j];
        return;
    }

    // ---------------- gemm_p part: P = points @ W1p^T ----------------
    const int s = blockIdx.x - 128;          // 0..1023
    if (s < 256) {                           // fused W2 bf16 hi/lo split
        int i = s * 256 + threadIdx.x;
        float v = W2[i];
        __nv_bfloat16 h = __float2bfloat16(v);
        g_Bhi[i] = h;
        g_Blo[i] = __float2bfloat16(v - __bfloat162float(h));
    }

    float (*As)[128] = reinterpret_cast<float(*)[128]>(smem_u);
    float (*Bs)[128] = reinterpret_cast<float(*)[128]>(smem_u + 8192);

    const int t  = threadIdx.x;
    const int tx = t & 15, ty = t >> 4;
    const int rowBase = (s >> 1) * 128;      // 512 row-tiles
    const int colBase = (s & 1) * 128;       // 2 col-tiles

    float acc[8][8];
#pragma unroll
    for (int i = 0; i < 8; i++)
#pragma unroll
        for (int j = 0; j < 8; j++) acc[i][j] = 0.f;

    for (int k0 = 0; k0 < CC; k0 += 16) {
#pragma unroll
        for (int l = 0; l < 2; l++) {
            int fid = t + l*256;
            int row = fid >> 2, c4 = (fid & 3) * 4;
            float4 v = *(const float4*)(points + (size_t)(rowBase + row)*CC + k0 + c4);
            As[c4+0][row] = v.x; As[c4+1][row] = v.y;
            As[c4+2][row] = v.z; As[c4+3][row] = v.w;
        }
#pragma unroll
        for (int l = 0; l < 8; l++) {
            int e = t + l*256;
            int c = e & 15, o = e >> 4;
            Bs[c][o] = W1[(size_t)(colBase + o)*CI1 + 3 + k0 + c];
        }
        __syncthreads();
#pragma unroll
        for (int kk = 0; kk < 16; kk++) {
            float4 a0 = *(const float4*)&As[kk][ty*8];
            float4 a1 = *(const float4*)&As[kk][ty*8+4];
            float4 b0 = *(const float4*)&Bs[kk][tx*8];
            float4 b1 = *(const float4*)&Bs[kk][tx*8+4];
            float aR[8] = {a0.x,a0.y,a0.z,a0.w,a1.x,a1.y,a1.z,a1.w};
            float bR[8] = {b0.x,b0.y,b0.z,b0.w,b1.x,b1.y,b1.z,b1.w};
#pragma unroll
            for (int i = 0; i < 8; i++)
#pragma unroll
                for (int j = 0; j < 8; j++)
                    acc[i][j] = fmaf(aR[i], bR[j], acc[i][j]);
        }
        __syncthreads();
    }
#pragma unroll
    for (int i = 0; i < 8; i++) {
        int row = rowBase + ty*8 + i;
        float* cp = g_P + (size_t)row*CO + colBase + tx*8;
        *(float4*)cp       = make_float4(acc[i][0], acc[i][1], acc[i][2], acc[i][3]);
        *(float4*)(cp + 4) = make_float4(acc[i][4], acc[i][5], acc[i][6], acc[i][7]);
    }
}

// ========== launch 1: BN1 stats only (no h1 materialization) ==================
__global__ __launch_bounds__(256)
void stats1_kernel(const float* __restrict__ pos, const int* __restrict__ idx,
                   const float* __restrict__ W1, const float* __restrict__ b1)
{
    const int RPB = 64;
    __shared__ int   s_pb[RPB];
    __shared__ float s_r[RPB][3];
    const int base = blockIdx.x * RPB;
    const int t = threadIdx.x;
    if (t < RPB) {
        int r  = base + t;
        int b  = r >> 16;
        int m  = (r >> 4) & 4095;
        int nn = g_knn[r];
        const float* pb = pos + (size_t)b * NN * 3;
        int nq = idx[b*MM + m];
        s_r[t][0] = pb[nn*3+0] - pb[nq*3+0];
        s_r[t][1] = pb[nn*3+1] - pb[nq*3+1];
        s_r[t][2] = pb[nn*3+2] - pb[nq*3+2];
        s_pb[t]   = (b*NN + nn) * CO;
    }
    __syncthreads();
    const int o = t;
    const float w0 = W1[o*CI1+0], w1 = W1[o*CI1+1], w2 = W1[o*CI1+2], bb = b1[o];
    float ls = 0.f, lss = 0.f;
#pragma unroll 4
    for (int rr = 0; rr < RPB; rr++) {
        float v = g_P[(size_t)s_pb[rr] + o];
        v = v + bb + w0*s_r[rr][0] + w1*s_r[rr][1] + w2*s_r[rr][2];
        ls += v; lss += v*v;
    }
    atomicAdd(&g_sum1[o], ls);
    atomicAdd(&g_sumsq1[o], lss);
}

// ========== launch 2: GEMM2 (bf16 3-term mma.sync) with inline P-gather =======
// SMEM map:
//   [0,4096)        s_cc  float4[256] = {sc, c0, sc*w0, sc*w1}
//   [4096,5120)     s_w2c float[256]  = sc*w2
//   [5120,6144)     s_b2  float[256]
//   [6144,6656)     s_pb  int[128]
//   [6656,8192)     s_r   float[128][3]
//   [8192,+67584)   B hi (528 B/row x 128)
//   [75776,+67584)  B lo
//   [143360,+40960) A double-buffered (hi+lo per buf, 80 B/row)
#define SM2_CC   0
#define SM2_W2C  4096
#define SM2_B2   5120
#define SM2_PB   6144
#define SM2_R    6656
#define SM2_BHI  8192
#define SM2_BLO  (SM2_BHI + 67584)
#define SM2_A    (SM2_BLO + 67584)     // 143360
#define SM2_ABUF 20480
#define SMEM_G2  (SM2_A + 2*SM2_ABUF)  // 184320

__device__ __forceinline__ void mma16816(float* c, const uint32_t* a,
                                         uint32_t b0, uint32_t b1) {
    asm volatile(
        "mma.sync.aligned.m16n8k16.row.col.f32.bf16.bf16.f32 "
        "{%0,%1,%2,%3}, {%4,%5,%6,%7}, {%8,%9}, {%0,%1,%2,%3};\n"
        : "+f"(c[0]), "+f"(c[1]), "+f"(c[2]), "+f"(c[3])
        : "r"(a[0]), "r"(a[1]), "r"(a[2]), "r"(a[3]), "r"(b0), "r"(b1));
}
__device__ __forceinline__ void ldsm_x4(uint32_t* r, uint32_t addr) {
    asm volatile("ldmatrix.sync.aligned.m8n8.x4.shared.b16 {%0,%1,%2,%3}, [%4];"
                 : "=r"(r[0]), "=r"(r[1]), "=r"(r[2]), "=r"(r[3]) : "r"(addr));
}
__device__ __forceinline__ uint32_t cvt_bf2(float lo, float hi) {
    __nv_bfloat162 h = __float22bfloat162_rn(make_float2(lo, hi));
    return *reinterpret_cast<uint32_t*>(&h);
}

__global__ __launch_bounds__(512, 1)
void gemm2_mma_kernel(const float* __restrict__ b2,
                      const float* __restrict__ g1, const float* __restrict__ beta1,
                      const float* __restrict__ W1, const float* __restrict__ b1,
                      const float* __restrict__ pos, const int* __restrict__ idx)
{
    extern __shared__ char smx[];
    float4* s_cc  = (float4*)(smx + SM2_CC);
    float*  s_w2c = (float*)(smx + SM2_W2C);
    float*  s_b2  = (float*)(smx + SM2_B2);
    int*    s_pb  = (int*)(smx + SM2_PB);
    float (*s_r)[3] = reinterpret_cast<float(*)[3]>(smx + SM2_R);
    char*  sBhi = smx + SM2_BHI;
    char*  sBlo = smx + SM2_BLO;

    const int t    = threadIdx.x;
    const int lane = t & 31, wid = t >> 5;
    const int warp_m = wid & 3;
    const int warp_n = wid >> 2;
    const int nh   = blockIdx.x & 1;

    const uint32_t smemBase = (uint32_t)__cvta_generic_to_shared(smx);

    // fused BN1 finalize + per-channel fused constants
    if (t < 256) {
        const float inv = 1.0f / (float)ROWS;
        float mean = g_sum1[t] * inv;
        float var  = g_sumsq1[t] * inv - mean*mean;
        float sc = g1[t] * rsqrtf(var + 1e-5f);
        float sh = fmaf(-mean, sc, beta1[t]);
        float w0 = W1[t*CI1+0], w1 = W1[t*CI1+1], w2 = W1[t*CI1+2];
        s_cc[t]  = make_float4(sc, fmaf(sc, b1[t], sh), sc*w0, sc*w1);
        s_w2c[t] = sc*w2;
        s_b2[t]  = b2[t];
    }

    // resident B half (hi/lo)
#pragma unroll
    for (int l = 0; l < 8; l++) {
        int e = t + l*512;
        int n = e >> 5, k8 = e & 31;
        size_t gsrc = ((size_t)(nh*128 + n))*CO + k8*8;
        *(uint4*)(sBhi + n*528 + k8*16) = *(const uint4*)(g_Bhi + gsrc);
        *(uint4*)(sBlo + n*528 + k8*16) = *(const uint4*)(g_Blo + gsrc);
    }

    float st_s[4][2], st_q[4][2];
    const int colb = nh*128 + warp_n*32 + 2*(lane & 3);
#pragma unroll
    for (int j = 0; j < 4; j++) {
        st_s[j][0] = st_s[j][1] = 0.f;
        st_q[j][0] = st_q[j][1] = 0.f;
    }

    const int aM = warp_m*32 + (lane & 7) + ((lane >> 3) & 1)*8;
    const uint32_t aLane = (uint32_t)(aM*80 + (lane >> 4)*16);
    const uint32_t aBase0 = smemBase + SM2_A + aLane;
    const uint32_t aBase1 = smemBase + SM2_A + SM2_ABUF + aLane;
    const int bN = warp_n*32 + (lane & 7) + (lane >> 4)*8;
    const uint32_t bKoff = ((lane >> 3) & 1)*16;
    const uint32_t bLaneHi = smemBase + SM2_BHI + bN*528 + bKoff;
    const uint32_t bLaneLo = smemBase + SM2_BLO + bN*528 + bKoff;

    const int qrow = t >> 2;
    const int kq   = (t & 3) * 8;

    for (int wi = blockIdx.x; wi < NWORK; wi += gridDim.x) {
        const int mtile = wi >> 1;
        const int rowBase = mtile * 128;

        // per-tile row info (gather indices + rel coords)
        if (t < 128) {
            int r  = rowBase + t;
            int b  = r >> 16;
            int m  = (r >> 4) & 4095;
            int nn = g_knn[r];
            const float* pb = pos + (size_t)b * NN * 3;
            int nq = idx[b*MM + m];
            s_r[t][0] = pb[nn*3+0] - pb[nq*3+0];
            s_r[t][1] = pb[nn*3+1] - pb[nq*3+1];
            s_r[t][2] = pb[nn*3+2] - pb[nq*3+2];
            s_pb[t]   = (b*NN + nn) * CO;
        }
        __syncthreads();   // row info ready (also first-iter: params/B ready)

        const int   pbase = s_pb[qrow];
        const float r0 = s_r[qrow][0], r1 = s_r[qrow][1], r2 = s_r[qrow][2];

        float acc[2][4][4];
#pragma unroll
        for (int i = 0; i < 2; i++)
#pragma unroll
            for (int j = 0; j < 4; j++)
#pragma unroll
                for (int d = 0; d < 4; d++) acc[i][j][d] = 0.f;

        // prefetch chunk 0 (8 channels of this thread's row, from L2-resident P)
        float4 pf0, pf1;
        {
            const float4* src = (const float4*)(g_P + (size_t)pbase + kq);
            pf0 = src[0]; pf1 = src[1];
        }

        for (int c = 0; c < 8; c++) {
            const int buf = c & 1;
            // BN1+ReLU via fused constants, hi/lo split, store to A buf
            {
                char* aH = smx + SM2_A + buf*SM2_ABUF + qrow*80 + kq*2;
                const int cb = c*32 + kq;
                float x[8] = {pf0.x, pf0.y, pf0.z, pf0.w, pf1.x, pf1.y, pf1.z, pf1.w};
#pragma unroll
                for (int v = 0; v < 8; v++) {
                    float4 cc = s_cc[cb+v];
                    float off = fmaf(s_w2c[cb+v], r2,
                                fmaf(cc.w, r1, fmaf(cc.z, r0, cc.y)));
                    x[v] = fmaxf(0.f, fmaf(x[v], cc.x, off));
                }
                uint32_t uh[4], ul[4];
#pragma unroll
                for (int p = 0; p < 4; p++) uh[p] = cvt_bf2(x[2*p], x[2*p+1]);
#pragma unroll
                for (int p = 0; p < 4; p++) {
                    float l0 = x[2*p]   - __uint_as_float(uh[p] << 16);
                    float l1 = x[2*p+1] - __uint_as_float(uh[p] & 0xffff0000u);
                    ul[p] = cvt_bf2(l0, l1);
                }
                *(uint4*)(aH)         = make_uint4(uh[0], uh[1], uh[2], uh[3]);
                *(uint4*)(aH + 10240) = make_uint4(ul[0], ul[1], ul[2], ul[3]);
            }
            if (c < 7) {
                const float4* src = (const float4*)(g_P + (size_t)pbase
                                                    + (c+1)*32 + kq);
                pf0 = src[0]; pf1 = src[1];
            }
            __syncthreads();   // A chunk ready (double-buffered, 1 barrier/chunk)

            const uint32_t aAddr = (buf ? aBase1 : aBase0);
#pragma unroll
            for (int ks = 0; ks < 2; ks++) {
                uint32_t aHf[2][4], aLf[2][4], bHf[2][4], bLf[2][4];
#pragma unroll
                for (int i = 0; i < 2; i++) {
                    ldsm_x4(aHf[i], aAddr + (uint32_t)(i*1280 + ks*32));
                    ldsm_x4(aLf[i], aAddr + (uint32_t)(10240 + i*1280 + ks*32));
                }
                const uint32_t cb2 = (uint32_t)(c*64 + ks*32);
#pragma unroll
                for (int jp = 0; jp < 2; jp++) {
                    ldsm_x4(bHf[jp], bLaneHi + (uint32_t)(jp*8448) + cb2);
                    ldsm_x4(bLf[jp], bLaneLo + (uint32_t)(jp*8448) + cb2);
                }
#pragma unroll
                for (int j = 0; j < 4; j++)
#pragma unroll
                    for (int i = 0; i < 2; i++)
                        mma16816(acc[i][j], aHf[i],
                                 bHf[j>>1][(j&1)*2], bHf[j>>1][(j&1)*2+1]);
#pragma unroll
                for (int j = 0; j < 4; j++)
#pragma unroll
                    for (int i = 0; i < 2; i++)
                        mma16816(acc[i][j], aLf[i],
                                 bHf[j>>1][(j&1)*2], bHf[j>>1][(j&1)*2+1]);
#pragma unroll
                for (int j = 0; j < 4; j++)
#pragma unroll
                    for (int i = 0; i < 2; i++)
                        mma16816(acc[i][j], aHf[i],
                                 bLf[j>>1][(j&1)*2], bLf[j>>1][(j&1)*2+1]);
            }
        }

        // ---- fused epilogue: bias + stats + 16-row max/min pool ----
#pragma unroll
        for (int i = 0; i < 2; i++) {
            int q = mtile*8 + warp_m*2 + i;
#pragma unroll
            for (int j = 0; j < 4; j++) {
                float bb0 = s_b2[nh*128 + warp_n*32 + j*8 + 2*(lane & 3)];
                float bb1 = s_b2[nh*128 + warp_n*32 + j*8 + 2*(lane & 3) + 1];
                float v0 = acc[i][j][0] + bb0;
                float v1 = acc[i][j][1] + bb1;
                float v2 = acc[i][j][2] + bb0;
                float v3 = acc[i][j][3] + bb1;
                st_s[j][0] += v0 + v2;
                st_q[j][0] += v0*v0 + v2*v2;
                st_s[j][1] += v1 + v3;
                st_q[j][1] += v1*v1 + v3*v3;
                float mx0 = fmaxf(v0, v2), mn0 = fminf(v0, v2);
                float mx1 = fmaxf(v1, v3), mn1 = fminf(v1, v3);
#pragma unroll
                for (int s = 4; s <= 16; s <<= 1) {
                    mx0 = fmaxf(mx0, __shfl_xor_sync(0xffffffffu, mx0, s));
                    mn0 = fminf(mn0, __shfl_xor_sync(0xffffffffu, mn0, s));
                    mx1 = fmaxf(mx1, __shfl_xor_sync(0xffffffffu, mx1, s));
                    mn1 = fminf(mn1, __shfl_xor_sync(0xffffffffu, mn1, s));
                }
                if (lane < 4) {
                    int col = nh*128 + warp_n*32 + j*8 + 2*lane;
                    g_hmax[(size_t)q*CO + col]     = mx0;
                    g_hmax[(size_t)q*CO + col + 1] = mx1;
                    g_hmin[(size_t)q*CO + col]     = mn0;
                    g_hmin[(size_t)q*CO + col + 1] = mn1;
                }
            }
        }
    }

#pragma unroll
    for (int j = 0; j < 4; j++) {
        atomicAdd(&g_sum2  [colb + j*8],     st_s[j][0]);
        atomicAdd(&g_sumsq2[colb + j*8],     st_q[j][0]);
        atomicAdd(&g_sum2  [colb + j*8 + 1], st_s[j][1]);
        atomicAdd(&g_sumsq2[colb + j*8 + 1], st_q[j][1]);
    }
}

// ========== launch 3: BN2 finalize + pooled output ============================
__global__ __launch_bounds__(256)
void final_out_kernel(float* __restrict__ out,
                      const float* __restrict__ g2, const float* __restrict__ beta2)
{
    __shared__ float s_sc2[CO], s_sh2[CO];
    {
        int o = threadIdx.x;
        const float inv = 1.0f / (float)ROWS;
        float mean = g_sum2[o] * inv;
        float var  = g_sumsq2[o] * inv - mean*mean;
        float s = g2[o] * rsqrtf(var + 1e-5f);
        s_sc2[o] = s;
        s_sh2[o] = fmaf(-mean, s, beta2[o]);
    }
    __syncthreads();

    int t = blockIdx.x * 256 + threadIdx.x;
    int row = t >> 6, cg = t & 63;
    int c = cg * 4;
    float4 mx = *(const float4*)(g_hmax + (size_t)row*CO + c);
    float4 mn = *(const float4*)(g_hmin + (size_t)row*CO + c);
    float s0 = s_sc2[c+0], s1 = s_sc2[c+1], s2 = s_sc2[c+2], s3 = s_sc2[c+3];
    float h0 = s_sh2[c+0], h1 = s_sh2[c+1], h2 = s_sh2[c+2], h3 = s_sh2[c+3];
    float4 r;
    r.x = fmaxf(0.f, fmaf(s0 >= 0.f ? mx.x : mn.x, s0, h0));
    r.y = fmaxf(0.f, fmaf(s1 >= 0.f ? mx.y : mn.y, s1, h1));
    r.z = fmaxf(0.f, fmaf(s2 >= 0.f ? mx.z : mn.z, s2, h2));
    r.w = fmaxf(0.f, fmaf(s3 >= 0.f ? mx.w : mn.w, s3, h3));
    *(float4*)(out + NEWPOS_ELEMS + (size_t)row*CO + c) = r;
}

// ---------------- launch ----------------
extern "C" void kernel_launch(void* const* d_in, const int* in_sizes, int n_in,
                              void* d_out, int out_size)
{
    const float* pos    = (const float*)d_in[0];
    const float* points = (const float*)d_in[1];
    const int*   idx    = (const int*)  d_in[2];
    const float* W1     = (const float*)d_in[3];
    const float* b1     = (const float*)d_in[4];
    const float* g1     = (const float*)d_in[5];
    const float* beta1  = (const float*)d_in[6];
    const float* W2     = (const float*)d_in[7];
    const float* b2     = (const float*)d_in[8];
    const float* g2     = (const float*)d_in[9];
    const float* beta2  = (const float*)d_in[10];
    float* out = (float*)d_out;

    cudaFuncSetAttribute(gemm2_mma_kernel,
                         cudaFuncAttributeMaxDynamicSharedMemorySize, SMEM_G2);

    // launch 0: kNN + gemm_p co-scheduled (+ stat zeroing, W2 split)
    knn_gemmp_kernel<<<1152, 256>>>(pos, idx, out, points, W1, W2);
    // launch 1: BN1 stats via L2-resident P gather (no h1 materialization)
    stats1_kernel<<<ROWS/64, 256>>>(pos, idx, W1, b1);
    // launch 2: GEMM2 with inline P-gather loader + pooled epilogue
    gemm2_mma_kernel<<<148, 512, SMEM_G2>>>(b2, g1, beta1, W1, b1, pos, idx);
    // launch 3: BN2 finalize + output
    final_out_kernel<<<(QTOT*64)/256, 256>>>(out, g2, beta2);
}

// round 15
// speedup vs baseline: 1.2296x; 1.2296x over previous
#include <cuda_runtime.h>
#include <cuda_bf16.h>
#include <float.h>
#include <cstdint>

// Problem constants
#define BB   8
#define NN   8192
#define MM   4096
#define CC   128
#define KNN  16
#define CO   256
#define CI1  131
#define ROWS (BB*MM*KNN)  // 524288
#define QTOT (BB*MM)      // 32768
#define NEWPOS_ELEMS (QTOT*3)
#define NTILE (ROWS/128)        // 4096
#define NWORK (2*NTILE)         // 8192

// ---------------- static scratch (allocation-free rule) ----------------
__device__ float g_P [ (size_t)BB*NN*CO ];       // 64 MB   points @ W1p^T
__device__ float g_h1[ (size_t)ROWS*CO ];        // 512 MB  layer1 pre-activations
__device__ float g_hmax[ (size_t)QTOT*CO ];      // 32 MB
__device__ float g_hmin[ (size_t)QTOT*CO ];      // 32 MB
__device__ int   g_knn[ ROWS ];                  // 2 MB
__device__ __nv_bfloat16 g_Bhi[CO*CO];
__device__ __nv_bfloat16 g_Blo[CO*CO];
__device__ float g_sum1[CO], g_sumsq1[CO], g_sum2[CO], g_sumsq2[CO];

// ========== launch 0: fused kNN (blocks 0..127) + gemm_p/W2split (128..1151) ==
__global__ __launch_bounds__(256)
void knn_gemmp_kernel(const float* __restrict__ pos, const int* __restrict__ idx,
                      float* __restrict__ out_newpos,
                      const float* __restrict__ points,
                      const float* __restrict__ W1, const float* __restrict__ W2)
{
    __shared__ char smem_u[32768];

    if (blockIdx.x < 128) {
        // ---------------- kNN part ----------------
        if (blockIdx.x == 0 && threadIdx.x < CO) {
            int tt = threadIdx.x;
            g_sum1[tt] = 0.f;  g_sumsq1[tt] = 0.f;
            g_sum2[tt] = 0.f;  g_sumsq2[tt] = 0.f;
        }
        float4* sp = reinterpret_cast<float4*>(smem_u);
        const int q = blockIdx.x * 256 + threadIdx.x;
        const int b = q >> 12;
        const float* pb = pos + (size_t)b * NN * 3;

        const int nq = idx[q];
        const float qx = pb[nq*3+0], qy = pb[nq*3+1], qz = pb[nq*3+2];
        out_newpos[q*3+0] = qx; out_newpos[q*3+1] = qy; out_newpos[q*3+2] = qz;
        const float qn = qx*qx + qy*qy + qz*qz;

        float dist[KNN]; int ind[KNN];
#pragma unroll
        for (int j = 0; j < KNN; j++) { dist[j] = FLT_MAX; ind[j] = 0x7fffffff; }

        for (int c0 = 0; c0 < NN; c0 += 2048) {
            __syncthreads();
            for (int i = threadIdx.x; i < 2048; i += 256) {
                float x = pb[(c0+i)*3+0], y = pb[(c0+i)*3+1], z = pb[(c0+i)*3+2];
                sp[i] = make_float4(x, y, z, x*x + y*y + z*z);
            }
            __syncthreads();
#pragma unroll 4
            for (int i = 0; i < 2048; i++) {
                float4 p = sp[i];
                float qp = qx*p.x + qy*p.y + qz*p.z;
                float d  = qn - 2.0f*qp + p.w;
                if (d < dist[0]) {
                    const int nidx = c0 + i;
                    bool prev = true;
#pragma unroll
                    for (int j = 0; j < KNN-1; j++) {
                        bool nxt = d < dist[j+1];
                        float dj = nxt ? dist[j+1] : (prev ? d    : dist[j]);
                        int   ij = nxt ? ind[j+1]  : (prev ? nidx : ind[j]);
                        dist[j] = dj; ind[j] = ij;
                        prev = nxt;
                    }
                    if (prev) { dist[KNN-1] = d; ind[KNN-1] = nidx; }
                }
            }
        }
#pragma unroll
        for (int j = 0; j < KNN; j++) g_knn[q*KNN + j] = ind[j];
        return;
    }

    // ---------------- gemm_p part: P = points @ W1p^T ----------------
    const int s = blockIdx.x - 128;          // 0..1023
    if (s < 256) {                           // fused W2 bf16 hi/lo split
        int i = s * 256 + threadIdx.x;
        float v = W2[i];
        __nv_bfloat16 h = __float2bfloat16(v);
        g_Bhi[i] = h;
        g_Blo[i] = __float2bfloat16(v - __bfloat162float(h));
    }

    float (*As)[128] = reinterpret_cast<float(*)[128]>(smem_u);
    float (*Bs)[128] = reinterpret_cast<float(*)[128]>(smem_u + 8192);

    const int t  = threadIdx.x;
    const int tx = t & 15, ty = t >> 4;
    const int rowBase = (s >> 1) * 128;      // 512 row-tiles
    const int colBase = (s & 1) * 128;       // 2 col-tiles

    float acc[8][8];
#pragma unroll
    for (int i = 0; i < 8; i++)
#pragma unroll
        for (int j = 0; j < 8; j++) acc[i][j] = 0.f;

    for (int k0 = 0; k0 < CC; k0 += 16) {
#pragma unroll
        for (int l = 0; l < 2; l++) {
            int fid = t + l*256;
            int row = fid >> 2, c4 = (fid & 3) * 4;
            float4 v = *(const float4*)(points + (size_t)(rowBase + row)*CC + k0 + c4);
            As[c4+0][row] = v.x; As[c4+1][row] = v.y;
            As[c4+2][row] = v.z; As[c4+3][row] = v.w;
        }
#pragma unroll
        for (int l = 0; l < 8; l++) {
            int e = t + l*256;
            int c = e & 15, o = e >> 4;
            Bs[c][o] = W1[(size_t)(colBase + o)*CI1 + 3 + k0 + c];
        }
        __syncthreads();
#pragma unroll
        for (int kk = 0; kk < 16; kk++) {
            float4 a0 = *(const float4*)&As[kk][ty*8];
            float4 a1 = *(const float4*)&As[kk][ty*8+4];
            float4 b0 = *(const float4*)&Bs[kk][tx*8];
            float4 b1 = *(const float4*)&Bs[kk][tx*8+4];
            float aR[8] = {a0.x,a0.y,a0.z,a0.w,a1.x,a1.y,a1.z,a1.w};
            float bR[8] = {b0.x,b0.y,b0.z,b0.w,b1.x,b1.y,b1.z,b1.w};
#pragma unroll
            for (int i = 0; i < 8; i++)
#pragma unroll
                for (int j = 0; j < 8; j++)
                    acc[i][j] = fmaf(aR[i], bR[j], acc[i][j]);
        }
        __syncthreads();
    }
#pragma unroll
    for (int i = 0; i < 8; i++) {
        int row = rowBase + ty*8 + i;
        float* cp = g_P + (size_t)row*CO + colBase + tx*8;
        *(float4*)cp       = make_float4(acc[i][0], acc[i][1], acc[i][2], acc[i][3]);
        *(float4*)(cp + 4) = make_float4(acc[i][4], acc[i][5], acc[i][6], acc[i][7]);
    }
}

// ========== launch 1: assemble h1 = P[knn] + W1r*rel + b1  (+ stats) ==========
__global__ __launch_bounds__(256)
void assemble_h1_kernel(const float* __restrict__ pos, const int* __restrict__ idx,
                        const float* __restrict__ W1, const float* __restrict__ b1)
{
    const int RPB = 64;
    __shared__ int   s_pb[RPB];
    __shared__ float s_r[RPB][3];
    const int base = blockIdx.x * RPB;
    const int t = threadIdx.x;
    if (t < RPB) {
        int r  = base + t;
        int b  = r >> 16;
        int m  = (r >> 4) & 4095;
        int nn = g_knn[r];
        const float* pb = pos + (size_t)b * NN * 3;
        int nq = idx[b*MM + m];
        s_r[t][0] = pb[nn*3+0] - pb[nq*3+0];
        s_r[t][1] = pb[nn*3+1] - pb[nq*3+1];
        s_r[t][2] = pb[nn*3+2] - pb[nq*3+2];
        s_pb[t]   = (b*NN + nn) * CO;
    }
    __syncthreads();
    const int o = t;
    const float w0 = W1[o*CI1+0], w1 = W1[o*CI1+1], w2 = W1[o*CI1+2], bb = b1[o];
    float ls = 0.f, lss = 0.f;
#pragma unroll 4
    for (int rr = 0; rr < RPB; rr++) {
        float v = g_P[(size_t)s_pb[rr] + o];
        v = v + bb + w0*s_r[rr][0] + w1*s_r[rr][1] + w2*s_r[rr][2];
        g_h1[(size_t)(base + rr)*CO + o] = v;
        ls += v; lss += v*v;
    }
    atomicAdd(&g_sum1[o], ls);
    atomicAdd(&g_sumsq1[o], lss);
}

// ========== launch 2: GEMM2 via mma.sync bf16 (3-term split), 512 threads =====
#define SM2_SC   0
#define SM2_SH   1024
#define SM2_B2   2048
#define SM2_BHI  3072
#define SM2_BLO  (SM2_BHI + 67584)
#define SM2_A    (SM2_BLO + 67584)     // 138240
#define SM2_ABUF 20480                 // one buffer = hi(10240) + lo(10240)
#define SMEM_G2  (SM2_A + 2*SM2_ABUF)  // 179200 bytes

__device__ __forceinline__ void mma16816(float* c, const uint32_t* a,
                                         uint32_t b0, uint32_t b1) {
    asm volatile(
        "mma.sync.aligned.m16n8k16.row.col.f32.bf16.bf16.f32 "
        "{%0,%1,%2,%3}, {%4,%5,%6,%7}, {%8,%9}, {%0,%1,%2,%3};\n"
        : "+f"(c[0]), "+f"(c[1]), "+f"(c[2]), "+f"(c[3])
        : "r"(a[0]), "r"(a[1]), "r"(a[2]), "r"(a[3]), "r"(b0), "r"(b1));
}
__device__ __forceinline__ void ldsm_x4(uint32_t* r, uint32_t addr) {
    asm volatile("ldmatrix.sync.aligned.m8n8.x4.shared.b16 {%0,%1,%2,%3}, [%4];"
                 : "=r"(r[0]), "=r"(r[1]), "=r"(r[2]), "=r"(r[3]) : "r"(addr));
}
__device__ __forceinline__ uint32_t cvt_bf2(float lo, float hi) {
    __nv_bfloat162 h = __float22bfloat162_rn(make_float2(lo, hi));
    return *reinterpret_cast<uint32_t*>(&h);
}

__global__ __launch_bounds__(512, 1)
void gemm2_mma_kernel(const float* __restrict__ b2,
                      const float* __restrict__ g1, const float* __restrict__ beta1)
{
    extern __shared__ char smx[];
    float* s_sc = (float*)(smx + SM2_SC);
    float* s_sh = (float*)(smx + SM2_SH);
    float* s_b2 = (float*)(smx + SM2_B2);
    char*  sBhi = smx + SM2_BHI;
    char*  sBlo = smx + SM2_BLO;

    const int t    = threadIdx.x;
    const int lane = t & 31, wid = t >> 5;
    const int warp_m = wid & 3;         // 0..3  -> 32-row quarter
    const int warp_n = wid >> 2;        // 0..3  -> 32-col slice
    const int nh   = blockIdx.x & 1;    // N-half

    const uint32_t smemBase = (uint32_t)__cvta_generic_to_shared(smx);

    // fused BN1 finalize (each CTA computes its own copy)
    if (t < 256) {
        const float inv = 1.0f / (float)ROWS;
        float mean = g_sum1[t] * inv;
        float var  = g_sumsq1[t] * inv - mean*mean;
        float s = g1[t] * rsqrtf(var + 1e-5f);
        s_sc[t] = s;
        s_sh[t] = fmaf(-mean, s, beta1[t]);
        s_b2[t] = b2[t];
    }

    // resident B half (hi/lo): 128 rows x 256 ch, padded rows of 528 B
#pragma unroll
    for (int l = 0; l < 8; l++) {
        int e = t + l*512;
        int n = e >> 5, k8 = e & 31;
        size_t gsrc = ((size_t)(nh*128 + n))*CO + k8*8;
        *(uint4*)(sBhi + n*528 + k8*16) = *(const uint4*)(g_Bhi + gsrc);
        *(uint4*)(sBlo + n*528 + k8*16) = *(const uint4*)(g_Blo + gsrc);
    }

    float st_s[4][2], st_q[4][2];
    const int colb = nh*128 + warp_n*32 + 2*(lane & 3);
#pragma unroll
    for (int j = 0; j < 4; j++) {
        st_s[j][0] = st_s[j][1] = 0.f;
        st_q[j][0] = st_q[j][1] = 0.f;
    }

    const int aM = warp_m*32 + (lane & 7) + ((lane >> 3) & 1)*8;
    const uint32_t aLane = (uint32_t)(aM*80 + (lane >> 4)*16);
    const uint32_t aBase0 = smemBase + SM2_A + aLane;
    const uint32_t aBase1 = smemBase + SM2_A + SM2_ABUF + aLane;
    const int bN = warp_n*32 + (lane & 7) + (lane >> 4)*8;
    const uint32_t bKoff = ((lane >> 3) & 1)*16;
    const uint32_t bLaneHi = smemBase + SM2_BHI + bN*528 + bKoff;
    const uint32_t bLaneLo = smemBase + SM2_BLO + bN*528 + bKoff;

    const int qrow = t >> 2;            // loader row 0..127
    const int kq   = (t & 3) * 8;       // loader 8-channel offset within 32-chunk

    __syncthreads();   // params + B resident visible before first use

    for (int wi = blockIdx.x; wi < NWORK; wi += gridDim.x) {
        const int mtile = wi >> 1;
        const size_t rowBase = (size_t)mtile * 128;

        float acc[2][4][4];
#pragma unroll
        for (int i = 0; i < 2; i++)
#pragma unroll
            for (int j = 0; j < 4; j++)
#pragma unroll
                for (int d = 0; d < 4; d++) acc[i][j][d] = 0.f;

        // prefetch chunk 0 (streaming, coalesced from g_h1)
        float4 pf0, pf1;
        {
            const float4* src = (const float4*)(g_h1 + (rowBase + qrow)*CO + kq);
            pf0 = src[0]; pf1 = src[1];
        }

        for (int c = 0; c < 8; c++) {
            const int buf = c & 1;
            // store prefetched chunk -> A buf with BN1+ReLU + hi/lo split
            {
                char* aH = smx + SM2_A + buf*SM2_ABUF + qrow*80 + kq*2;
                const int cb = c*32 + kq;
                float x[8] = {pf0.x, pf0.y, pf0.z, pf0.w, pf1.x, pf1.y, pf1.z, pf1.w};
#pragma unroll
                for (int v = 0; v < 8; v++)
                    x[v] = fmaxf(0.f, fmaf(x[v], s_sc[cb+v], s_sh[cb+v]));
                uint32_t uh[4], ul[4];
#pragma unroll
                for (int p = 0; p < 4; p++) uh[p] = cvt_bf2(x[2*p], x[2*p+1]);
#pragma unroll
                for (int p = 0; p < 4; p++) {
                    float l0 = x[2*p]   - __uint_as_float(uh[p] << 16);
                    float l1 = x[2*p+1] - __uint_as_float(uh[p] & 0xffff0000u);
                    ul[p] = cvt_bf2(l0, l1);
                }
                *(uint4*)(aH)         = make_uint4(uh[0], uh[1], uh[2], uh[3]);
                *(uint4*)(aH + 10240) = make_uint4(ul[0], ul[1], ul[2], ul[3]);
            }
            // prefetch next chunk (LDG latency overlaps mma below)
            if (c < 7) {
                const float4* src = (const float4*)(g_h1 + (rowBase + qrow)*CO
                                                    + (c+1)*32 + kq);
                pf0 = src[0]; pf1 = src[1];
            }
            __syncthreads();   // A chunk ready (double-buffered, 1 barrier/chunk)

            const uint32_t aAddr = (buf ? aBase1 : aBase0);
#pragma unroll
            for (int ks = 0; ks < 2; ks++) {
                uint32_t aHf[2][4], aLf[2][4], bHf[2][4], bLf[2][4];
#pragma unroll
                for (int i = 0; i < 2; i++) {
                    ldsm_x4(aHf[i], aAddr + (uint32_t)(i*1280 + ks*32));
                    ldsm_x4(aLf[i], aAddr + (uint32_t)(10240 + i*1280 + ks*32));
                }
                const uint32_t cb2 = (uint32_t)(c*64 + ks*32);
#pragma unroll
                for (int jp = 0; jp < 2; jp++) {
                    ldsm_x4(bHf[jp], bLaneHi + (uint32_t)(jp*8448) + cb2);
                    ldsm_x4(bLf[jp], bLaneLo + (uint32_t)(jp*8448) + cb2);
                }
#pragma unroll
                for (int j = 0; j < 4; j++)
#pragma unroll
                    for (int i = 0; i < 2; i++)
                        mma16816(acc[i][j], aHf[i],
                                 bHf[j>>1][(j&1)*2], bHf[j>>1][(j&1)*2+1]);
#pragma unroll
                for (int j = 0; j < 4; j++)
#pragma unroll
                    for (int i = 0; i < 2; i++)
                        mma16816(acc[i][j], aLf[i],
                                 bHf[j>>1][(j&1)*2], bHf[j>>1][(j&1)*2+1]);
#pragma unroll
                for (int j = 0; j < 4; j++)
#pragma unroll
                    for (int i = 0; i < 2; i++)
                        mma16816(acc[i][j], aHf[i],
                                 bLf[j>>1][(j&1)*2], bLf[j>>1][(j&1)*2+1]);
            }
        }

        // ---- fused epilogue: bias + stats + 16-row max/min pool ----
#pragma unroll
        for (int i = 0; i < 2; i++) {
            int q = mtile*8 + warp_m*2 + i;
#pragma unroll
            for (int j = 0; j < 4; j++) {
                float bb0 = s_b2[nh*128 + warp_n*32 + j*8 + 2*(lane & 3)];
                float bb1 = s_b2[nh*128 + warp_n*32 + j*8 + 2*(lane & 3) + 1];
                float v0 = acc[i][j][0] + bb0;
                float v1 = acc[i][j][1] + bb1;
                float v2 = acc[i][j][2] + bb0;
                float v3 = acc[i][j][3] + bb1;
                st_s[j][0] += v0 + v2;
                st_q[j][0] += v0*v0 + v2*v2;
                st_s[j][1] += v1 + v3;
                st_q[j][1] += v1*v1 + v3*v3;
                float mx0 = fmaxf(v0, v2), mn0 = fminf(v0, v2);
                float mx1 = fmaxf(v1, v3), mn1 = fminf(v1, v3);
#pragma unroll
                for (int s = 4; s <= 16; s <<= 1) {
                    mx0 = fmaxf(mx0, __shfl_xor_sync(0xffffffffu, mx0, s));
                    mn0 = fminf(mn0, __shfl_xor_sync(0xffffffffu, mn0, s));
                    mx1 = fmaxf(mx1, __shfl_xor_sync(0xffffffffu, mx1, s));
                    mn1 = fminf(mn1, __shfl_xor_sync(0xffffffffu, mn1, s));
                }
                if (lane < 4) {
                    int col = nh*128 + warp_n*32 + j*8 + 2*lane;
                    g_hmax[(size_t)q*CO + col]     = mx0;
                    g_hmax[(size_t)q*CO + col + 1] = mx1;
                    g_hmin[(size_t)q*CO + col]     = mn0;
                    g_hmin[(size_t)q*CO + col + 1] = mn1;
                }
            }
        }
    }

#pragma unroll
    for (int j = 0; j < 4; j++) {
        atomicAdd(&g_sum2  [colb + j*8],     st_s[j][0]);
        atomicAdd(&g_sumsq2[colb + j*8],     st_q[j][0]);
        atomicAdd(&g_sum2  [colb + j*8 + 1], st_s[j][1]);
        atomicAdd(&g_sumsq2[colb + j*8 + 1], st_q[j][1]);
    }
}

// ========== launch 3: BN2 finalize + pooled output ============================
__global__ __launch_bounds__(256)
void final_out_kernel(float* __restrict__ out,
                      const float* __restrict__ g2, const float* __restrict__ beta2)
{
    __shared__ float s_sc2[CO], s_sh2[CO];
    {
        int o = threadIdx.x;
        const float inv = 1.0f / (float)ROWS;
        float mean = g_sum2[o] * inv;
        float var  = g_sumsq2[o] * inv - mean*mean;
        float s = g2[o] * rsqrtf(var + 1e-5f);
        s_sc2[o] = s;
        s_sh2[o] = fmaf(-mean, s, beta2[o]);
    }
    __syncthreads();

    int t = blockIdx.x * 256 + threadIdx.x;
    int row = t >> 6, cg = t & 63;
    int c = cg * 4;
    float4 mx = *(const float4*)(g_hmax + (size_t)row*CO + c);
    float4 mn = *(const float4*)(g_hmin + (size_t)row*CO + c);
    float s0 = s_sc2[c+0], s1 = s_sc2[c+1], s2 = s_sc2[c+2], s3 = s_sc2[c+3];
    float h0 = s_sh2[c+0], h1 = s_sh2[c+1], h2 = s_sh2[c+2], h3 = s_sh2[c+3];
    float4 r;
    r.x = fmaxf(0.f, fmaf(s0 >= 0.f ? mx.x : mn.x, s0, h0));
    r.y = fmaxf(0.f, fmaf(s1 >= 0.f ? mx.y : mn.y, s1, h1));
    r.z = fmaxf(0.f, fmaf(s2 >= 0.f ? mx.z : mn.z, s2, h2));
    r.w = fmaxf(0.f, fmaf(s3 >= 0.f ? mx.w : mn.w, s3, h3));
    *(float4*)(out + NEWPOS_ELEMS + (size_t)row*CO + c) = r;
}

// ---------------- launch ----------------
extern "C" void kernel_launch(void* const* d_in, const int* in_sizes, int n_in,
                              void* d_out, int out_size)
{
    const float* pos    = (const float*)d_in[0];
    const float* points = (const float*)d_in[1];
    const int*   idx    = (const int*)  d_in[2];
    const float* W1     = (const float*)d_in[3];
    const float* b1     = (const float*)d_in[4];
    const float* g1     = (const float*)d_in[5];
    const float* beta1  = (const float*)d_in[6];
    const float* W2     = (const float*)d_in[7];
    const float* b2     = (const float*)d_in[8];
    const float* g2     = (const float*)d_in[9];
    const float* beta2  = (const float*)d_in[10];
    float* out = (float*)d_out;

    cudaFuncSetAttribute(gemm2_mma_kernel,
                         cudaFuncAttributeMaxDynamicSharedMemorySize, SMEM_G2);

    // launch 0: kNN + gemm_p co-scheduled (+ stat zeroing, W2 split)
    knn_gemmp_kernel<<<1152, 256>>>(pos, idx, out, points, W1, W2);
    // launch 1: h1 assembly + BN1 stats (streaming h1 write, P gather)
    assemble_h1_kernel<<<ROWS/64, 256>>>(pos, idx, W1, b1);
    // launch 2: GEMM2 (streams g_h1) + BN2 stats + pooled epilogue
    gemm2_mma_kernel<<<148, 512, SMEM_G2>>>(b2, g1, beta1);
    // launch 3: BN2 finalize + output
    final_out_kernel<<<(QTOT*64)/256, 256>>>(out, g2, beta2);
}

// round 16
// speedup vs baseline: 1.2771x; 1.0386x over previous
#include <cuda_runtime.h>
#include <cuda_bf16.h>
#include <float.h>
#include <cstdint>

// Problem constants
#define BB   8
#define NN   8192
#define MM   4096
#define CC   128
#define KNN  16
#define CO   256
#define CI1  131
#define ROWS (BB*MM*KNN)  // 524288
#define QTOT (BB*MM)      // 32768
#define NEWPOS_ELEMS (QTOT*3)
#define NTILE (ROWS/128)        // 4096
#define NWORK (2*NTILE)         // 8192

// ---------------- static scratch (allocation-free rule) ----------------
__device__ float g_P [ (size_t)BB*NN*CO ];       // 64 MB   points @ W1p^T
__device__ float g_h1[ (size_t)ROWS*CO ];        // 512 MB  layer1 pre-activations
__device__ float g_hmax[ (size_t)QTOT*CO ];      // 32 MB
__device__ float g_hmin[ (size_t)QTOT*CO ];      // 32 MB
__device__ int   g_knn[ ROWS ];                  // 2 MB
__device__ __nv_bfloat16 g_Bhi[CO*CO];
__device__ __nv_bfloat16 g_Blo[CO*CO];
__device__ float g_sum1[CO], g_sumsq1[CO], g_sum2[CO], g_sumsq2[CO];

// ========== launch 0: kNN (separate — co-scheduling regressed, R14) ==========
__global__ __launch_bounds__(256)
void knn_kernel(const float* __restrict__ pos, const int* __restrict__ idx,
                float* __restrict__ out_newpos)
{
    if (blockIdx.x == 0 && threadIdx.x < CO) {
        int tt = threadIdx.x;
        g_sum1[tt] = 0.f;  g_sumsq1[tt] = 0.f;
        g_sum2[tt] = 0.f;  g_sumsq2[tt] = 0.f;
    }

    __shared__ float4 sp[2048];
    const int q = blockIdx.x * 256 + threadIdx.x;
    const int b = q >> 12;
    const float* pb = pos + (size_t)b * NN * 3;

    const int nq = idx[q];
    const float qx = pb[nq*3+0], qy = pb[nq*3+1], qz = pb[nq*3+2];
    out_newpos[q*3+0] = qx; out_newpos[q*3+1] = qy; out_newpos[q*3+2] = qz;
    const float qn = qx*qx + qy*qy + qz*qz;

    float dist[KNN]; int ind[KNN];
#pragma unroll
    for (int j = 0; j < KNN; j++) { dist[j] = FLT_MAX; ind[j] = 0x7fffffff; }

    for (int c0 = 0; c0 < NN; c0 += 2048) {
        __syncthreads();
        for (int i = threadIdx.x; i < 2048; i += 256) {
            float x = pb[(c0+i)*3+0], y = pb[(c0+i)*3+1], z = pb[(c0+i)*3+2];
            sp[i] = make_float4(x, y, z, x*x + y*y + z*z);
        }
        __syncthreads();
#pragma unroll 4
        for (int i = 0; i < 2048; i++) {
            float4 p = sp[i];
            float qp = qx*p.x + qy*p.y + qz*p.z;
            float d  = qn - 2.0f*qp + p.w;
            if (d < dist[0]) {
                const int nidx = c0 + i;
                bool prev = true;
#pragma unroll
                for (int j = 0; j < KNN-1; j++) {
                    bool nxt = d < dist[j+1];
                    float dj = nxt ? dist[j+1] : (prev ? d    : dist[j]);
                    int   ij = nxt ? ind[j+1]  : (prev ? nidx : ind[j]);
                    dist[j] = dj; ind[j] = ij;
                    prev = nxt;
                }
                if (prev) { dist[KNN-1] = d; ind[KNN-1] = nidx; }
            }
        }
    }
#pragma unroll
    for (int j = 0; j < KNN; j++) g_knn[q*KNN + j] = ind[j];
}

// ========== launch 1: gemm_p (+ fused W2 split) ===============================
__global__ __launch_bounds__(256, 2)
void gemm_p_kernel(const float* __restrict__ A, int lda,
                   const float* __restrict__ Bw, int ldb, int boff,
                   float* __restrict__ C, int Kdim,
                   const float* __restrict__ W2)
{
    if (blockIdx.y == 0 && blockIdx.x < 256) {
        int i = blockIdx.x * 256 + threadIdx.x;
        float v = W2[i];
        __nv_bfloat16 h = __float2bfloat16(v);
        g_Bhi[i] = h;
        g_Blo[i] = __float2bfloat16(v - __bfloat162float(h));
    }

    const int BM = 128, BN = 128, BK = 16;
    __shared__ float As[BK][BM];
    __shared__ float Bs[BK][BN];

    const int t  = threadIdx.x;
    const int tx = t & 15, ty = t >> 4;
    const int rowBase = blockIdx.x * BM;
    const int colBase = blockIdx.y * BN;

    float acc[8][8];
#pragma unroll
    for (int i = 0; i < 8; i++)
#pragma unroll
        for (int j = 0; j < 8; j++) acc[i][j] = 0.f;

    for (int k0 = 0; k0 < Kdim; k0 += BK) {
#pragma unroll
        for (int l = 0; l < 2; l++) {
            int fid = t + l*256;
            int row = fid >> 2, c4 = (fid & 3) * 4;
            float4 v = *(const float4*)(A + (size_t)(rowBase + row)*lda + k0 + c4);
            As[c4+0][row] = v.x; As[c4+1][row] = v.y;
            As[c4+2][row] = v.z; As[c4+3][row] = v.w;
        }
#pragma unroll
        for (int l = 0; l < 8; l++) {
            int e = t + l*256;
            int c = e & 15, o = e >> 4;
            Bs[c][o] = Bw[(size_t)(colBase + o)*ldb + boff + k0 + c];
        }
        __syncthreads();
#pragma unroll
        for (int kk = 0; kk < BK; kk++) {
            float4 a0 = *(const float4*)&As[kk][ty*8];
            float4 a1 = *(const float4*)&As[kk][ty*8+4];
            float4 b0 = *(const float4*)&Bs[kk][tx*8];
            float4 b1 = *(const float4*)&Bs[kk][tx*8+4];
            float aR[8] = {a0.x,a0.y,a0.z,a0.w,a1.x,a1.y,a1.z,a1.w};
            float bR[8] = {b0.x,b0.y,b0.z,b0.w,b1.x,b1.y,b1.z,b1.w};
#pragma unroll
            for (int i = 0; i < 8; i++)
#pragma unroll
                for (int j = 0; j < 8; j++)
                    acc[i][j] = fmaf(aR[i], bR[j], acc[i][j]);
        }
        __syncthreads();
    }
#pragma unroll
    for (int i = 0; i < 8; i++) {
        int row = rowBase + ty*8 + i;
        float* cp = C + (size_t)row*CO + colBase + tx*8;
        *(float4*)cp       = make_float4(acc[i][0], acc[i][1], acc[i][2], acc[i][3]);
        *(float4*)(cp + 4) = make_float4(acc[i][4], acc[i][5], acc[i][6], acc[i][7]);
    }
}

// ========== launch 2: assemble h1 (+ BN1 stats) ===============================
__global__ __launch_bounds__(256)
void assemble_h1_kernel(const float* __restrict__ pos, const int* __restrict__ idx,
                        const float* __restrict__ W1, const float* __restrict__ b1)
{
    const int RPB = 64;
    __shared__ int   s_pb[RPB];
    __shared__ float s_r[RPB][3];
    const int base = blockIdx.x * RPB;
    const int t = threadIdx.x;
    if (t < RPB) {
        int r  = base + t;
        int b  = r >> 16;
        int m  = (r >> 4) & 4095;
        int nn = g_knn[r];
        const float* pb = pos + (size_t)b * NN * 3;
        int nq = idx[b*MM + m];
        s_r[t][0] = pb[nn*3+0] - pb[nq*3+0];
        s_r[t][1] = pb[nn*3+1] - pb[nq*3+1];
        s_r[t][2] = pb[nn*3+2] - pb[nq*3+2];
        s_pb[t]   = (b*NN + nn) * CO;
    }
    __syncthreads();
    const int o = t;
    const float w0 = W1[o*CI1+0], w1 = W1[o*CI1+1], w2 = W1[o*CI1+2], bb = b1[o];
    float ls = 0.f, lss = 0.f;
#pragma unroll 4
    for (int rr = 0; rr < RPB; rr++) {
        float v = g_P[(size_t)s_pb[rr] + o];
        v = v + bb + w0*s_r[rr][0] + w1*s_r[rr][1] + w2*s_r[rr][2];
        g_h1[(size_t)(base + rr)*CO + o] = v;
        ls += v; lss += v*v;
    }
    atomicAdd(&g_sum1[o], ls);
    atomicAdd(&g_sumsq1[o], lss);
}

// ========== launch 3: GEMM2, warp-specialized (4 producer + 16 consumer warps)
#define SM2_SC   0
#define SM2_SH   1024
#define SM2_B2   2048
#define SM2_BHI  3072
#define SM2_BLO  (SM2_BHI + 67584)
#define SM2_A    (SM2_BLO + 67584)     // 138240
#define SM2_ABUF 20480                 // one buffer = hi(10240) + lo(10240)
#define SMEM_G2  (SM2_A + 2*SM2_ABUF)  // 179200 bytes
#define G2_THREADS 640
// named barriers: full0=1, full1=2, empty0=3, empty1=4 (count = all 640)

__device__ __forceinline__ void mma16816(float* c, const uint32_t* a,
                                         uint32_t b0, uint32_t b1) {
    asm volatile(
        "mma.sync.aligned.m16n8k16.row.col.f32.bf16.bf16.f32 "
        "{%0,%1,%2,%3}, {%4,%5,%6,%7}, {%8,%9}, {%0,%1,%2,%3};\n"
        : "+f"(c[0]), "+f"(c[1]), "+f"(c[2]), "+f"(c[3])
        : "r"(a[0]), "r"(a[1]), "r"(a[2]), "r"(a[3]), "r"(b0), "r"(b1));
}
__device__ __forceinline__ void ldsm_x4(uint32_t* r, uint32_t addr) {
    asm volatile("ldmatrix.sync.aligned.m8n8.x4.shared.b16 {%0,%1,%2,%3}, [%4];"
                 : "=r"(r[0]), "=r"(r[1]), "=r"(r[2]), "=r"(r[3]) : "r"(addr));
}
__device__ __forceinline__ uint32_t cvt_bf2(float lo, float hi) {
    __nv_bfloat162 h = __float22bfloat162_rn(make_float2(lo, hi));
    return *reinterpret_cast<uint32_t*>(&h);
}
__device__ __forceinline__ void bar_sync(int id) {
    asm volatile("bar.sync %0, %1;" :: "r"(id), "r"(G2_THREADS) : "memory");
}
__device__ __forceinline__ void bar_arrive(int id) {
    asm volatile("bar.arrive %0, %1;" :: "r"(id), "r"(G2_THREADS) : "memory");
}
__device__ __forceinline__ void membar_cta() {
    asm volatile("membar.cta;" ::: "memory");
}

__global__ __launch_bounds__(G2_THREADS, 1)
void gemm2_mma_kernel(const float* __restrict__ b2,
                      const float* __restrict__ g1, const float* __restrict__ beta1)
{
    extern __shared__ char smx[];
    float* s_sc = (float*)(smx + SM2_SC);
    float* s_sh = (float*)(smx + SM2_SH);
    float* s_b2 = (float*)(smx + SM2_B2);
    char*  sBhi = smx + SM2_BHI;
    char*  sBlo = smx + SM2_BLO;

    const int t    = threadIdx.x;
    const int lane = t & 31, wid = t >> 5;
    const int nh   = blockIdx.x & 1;    // N-half (grid 148 even -> fixed)

    const uint32_t smemBase = (uint32_t)__cvta_generic_to_shared(smx);

    // fused BN1 finalize + params (all threads cooperate)
    if (t < 256) {
        const float inv = 1.0f / (float)ROWS;
        float mean = g_sum1[t] * inv;
        float var  = g_sumsq1[t] * inv - mean*mean;
        float s = g1[t] * rsqrtf(var + 1e-5f);
        s_sc[t] = s;
        s_sh[t] = fmaf(-mean, s, beta1[t]);
        s_b2[t] = b2[t];
    }
    // resident B half (hi/lo): 128 rows x 256 ch, rows of 528 B
    for (int e = t; e < 4096; e += G2_THREADS) {
        int n = e >> 5, k8 = e & 31;
        size_t gsrc = ((size_t)(nh*128 + n))*CO + k8*8;
        *(uint4*)(sBhi + n*528 + k8*16) = *(const uint4*)(g_Bhi + gsrc);
        *(uint4*)(sBlo + n*528 + k8*16) = *(const uint4*)(g_Blo + gsrc);
    }
    __syncthreads();   // params + B visible to all roles

    if (wid < 4) {
        // ================= PRODUCER (threads 0..127, one row each) ==========
        const int prow = t;                       // 0..127
        float4 pf[8];
        int wi = blockIdx.x;
        {
            const float4* src = (const float4*)(g_h1
                + ((size_t)(wi >> 1) * 128 + prow) * CO);
#pragma unroll
            for (int g = 0; g < 8; g++) pf[g] = src[g];
        }
        int cg = 0;
        for (; wi < NWORK; wi += 148) {
            const size_t rowB = (size_t)(wi >> 1) * 128;
#pragma unroll 1
            for (int c = 0; c < 8; c++) {
                const int buf = c & 1;
                if (cg >= 2) bar_sync(3 + buf);           // wait buffer free
                // BN1+ReLU + hi/lo split, store row chunk (32 ch) to A buf
                char* aH = smx + SM2_A + buf*SM2_ABUF + prow*80;
                char* aL = aH + 10240;
                const int cb = c*32;
#pragma unroll
                for (int g = 0; g < 4; g++) {
                    float4 f0 = pf[2*g], f1 = pf[2*g+1];
                    int ch = cb + g*8;
                    float x0 = fmaxf(0.f, fmaf(f0.x, s_sc[ch+0], s_sh[ch+0]));
                    float x1 = fmaxf(0.f, fmaf(f0.y, s_sc[ch+1], s_sh[ch+1]));
                    float x2 = fmaxf(0.f, fmaf(f0.z, s_sc[ch+2], s_sh[ch+2]));
                    float x3 = fmaxf(0.f, fmaf(f0.w, s_sc[ch+3], s_sh[ch+3]));
                    float x4 = fmaxf(0.f, fmaf(f1.x, s_sc[ch+4], s_sh[ch+4]));
                    float x5 = fmaxf(0.f, fmaf(f1.y, s_sc[ch+5], s_sh[ch+5]));
                    float x6 = fmaxf(0.f, fmaf(f1.z, s_sc[ch+6], s_sh[ch+6]));
                    float x7 = fmaxf(0.f, fmaf(f1.w, s_sc[ch+7], s_sh[ch+7]));
                    uint32_t h0 = cvt_bf2(x0, x1), h1 = cvt_bf2(x2, x3);
                    uint32_t h2 = cvt_bf2(x4, x5), h3 = cvt_bf2(x6, x7);
                    uint32_t l0 = cvt_bf2(x0 - __uint_as_float(h0 << 16),
                                          x1 - __uint_as_float(h0 & 0xffff0000u));
                    uint32_t l1 = cvt_bf2(x2 - __uint_as_float(h1 << 16),
                                          x3 - __uint_as_float(h1 & 0xffff0000u));
                    uint32_t l2 = cvt_bf2(x4 - __uint_as_float(h2 << 16),
                                          x5 - __uint_as_float(h2 & 0xffff0000u));
                    uint32_t l3 = cvt_bf2(x6 - __uint_as_float(h3 << 16),
                                          x7 - __uint_as_float(h3 & 0xffff0000u));
                    *(uint4*)(aH + g*16) = make_uint4(h0, h1, h2, h3);
                    *(uint4*)(aL + g*16) = make_uint4(l0, l1, l2, l3);
                }
                // prefetch next chunk into regs (overlaps consumer mma)
                {
                    int nc = c + 1;
                    size_t nrowB = rowB;
                    bool have = true;
                    if (nc == 8) {
                        nc = 0;
                        if (wi + 148 < NWORK) nrowB = (size_t)((wi + 148) >> 1) * 128;
                        else have = false;
                    }
                    if (have) {
                        const float4* src = (const float4*)(g_h1
                            + (nrowB + prow)*CO + nc*32);
#pragma unroll
                        for (int g = 0; g < 8; g++) pf[g] = src[g];
                    }
                }
                membar_cta();                              // STS visible
                bar_arrive(1 + buf);                       // signal buffer full
                cg++;
            }
        }
        return;
    }

    // ================= CONSUMER (16 warps, threads 128..639) ================
    const int cwid = wid - 4;
    const int warp_m = cwid & 3;        // 32-row quarter
    const int warp_n = cwid >> 2;       // 32-col slice

    float st_s[4][2], st_q[4][2];
    const int colb = nh*128 + warp_n*32 + 2*(lane & 3);
#pragma unroll
    for (int j = 0; j < 4; j++) {
        st_s[j][0] = st_s[j][1] = 0.f;
        st_q[j][0] = st_q[j][1] = 0.f;
    }

    const int aM = warp_m*32 + (lane & 7) + ((lane >> 3) & 1)*8;
    const uint32_t aLane = (uint32_t)(aM*80 + (lane >> 4)*16);
    const uint32_t aBase0 = smemBase + SM2_A + aLane;
    const uint32_t aBase1 = smemBase + SM2_A + SM2_ABUF + aLane;
    const int bN = warp_n*32 + (lane & 7) + (lane >> 4)*8;
    const uint32_t bKoff = ((lane >> 3) & 1)*16;
    const uint32_t bLaneHi = smemBase + SM2_BHI + bN*528 + bKoff;
    const uint32_t bLaneLo = smemBase + SM2_BLO + bN*528 + bKoff;

    for (int wi = blockIdx.x; wi < NWORK; wi += 148) {
        const int mtile = wi >> 1;

        float acc[2][4][4];
#pragma unroll
        for (int i = 0; i < 2; i++)
#pragma unroll
            for (int j = 0; j < 4; j++)
#pragma unroll
                for (int d = 0; d < 4; d++) acc[i][j][d] = 0.f;

#pragma unroll 1
        for (int c = 0; c < 8; c++) {
            const int buf = c & 1;
            bar_sync(1 + buf);                             // wait buffer full
            const uint32_t aAddr = (buf ? aBase1 : aBase0);
#pragma unroll
            for (int ks = 0; ks < 2; ks++) {
                uint32_t aHf[2][4], aLf[2][4], bHf[2][4], bLf[2][4];
#pragma unroll
                for (int i = 0; i < 2; i++) {
                    ldsm_x4(aHf[i], aAddr + (uint32_t)(i*1280 + ks*32));
                    ldsm_x4(aLf[i], aAddr + (uint32_t)(10240 + i*1280 + ks*32));
                }
                const uint32_t cb2 = (uint32_t)(c*64 + ks*32);
#pragma unroll
                for (int jp = 0; jp < 2; jp++) {
                    ldsm_x4(bHf[jp], bLaneHi + (uint32_t)(jp*8448) + cb2);
                    ldsm_x4(bLf[jp], bLaneLo + (uint32_t)(jp*8448) + cb2);
                }
#pragma unroll
                for (int j = 0; j < 4; j++)
#pragma unroll
                    for (int i = 0; i < 2; i++)
                        mma16816(acc[i][j], aHf[i],
                                 bHf[j>>1][(j&1)*2], bHf[j>>1][(j&1)*2+1]);
#pragma unroll
                for (int j = 0; j < 4; j++)
#pragma unroll
                    for (int i = 0; i < 2; i++)
                        mma16816(acc[i][j], aLf[i],
                                 bHf[j>>1][(j&1)*2], bHf[j>>1][(j&1)*2+1]);
#pragma unroll
                for (int j = 0; j < 4; j++)
#pragma unroll
                    for (int i = 0; i < 2; i++)
                        mma16816(acc[i][j], aHf[i],
                                 bLf[j>>1][(j&1)*2], bLf[j>>1][(j&1)*2+1]);
            }
            bar_arrive(3 + buf);                           // buffer free
        }

        // ---- fused epilogue: bias + stats + 16-row max/min pool ----
#pragma unroll
        for (int i = 0; i < 2; i++) {
            int q = mtile*8 + warp_m*2 + i;
#pragma unroll
            for (int j = 0; j < 4; j++) {
                float bb0 = s_b2[nh*128 + warp_n*32 + j*8 + 2*(lane & 3)];
                float bb1 = s_b2[nh*128 + warp_n*32 + j*8 + 2*(lane & 3) + 1];
                float v0 = acc[i][j][0] + bb0;
                float v1 = acc[i][j][1] + bb1;
                float v2 = acc[i][j][2] + bb0;
                float v3 = acc[i][j][3] + bb1;
                st_s[j][0] += v0 + v2;
                st_q[j][0] += v0*v0 + v2*v2;
                st_s[j][1] += v1 + v3;
                st_q[j][1] += v1*v1 + v3*v3;
                float mx0 = fmaxf(v0, v2), mn0 = fminf(v0, v2);
                float mx1 = fmaxf(v1, v3), mn1 = fminf(v1, v3);
#pragma unroll
                for (int s = 4; s <= 16; s <<= 1) {
                    mx0 = fmaxf(mx0, __shfl_xor_sync(0xffffffffu, mx0, s));
                    mn0 = fminf(mn0, __shfl_xor_sync(0xffffffffu, mn0, s));
                    mx1 = fmaxf(mx1, __shfl_xor_sync(0xffffffffu, mx1, s));
                    mn1 = fminf(mn1, __shfl_xor_sync(0xffffffffu, mn1, s));
                }
                if (lane < 4) {
                    int col = nh*128 + warp_n*32 + j*8 + 2*lane;
                    g_hmax[(size_t)q*CO + col]     = mx0;
                    g_hmax[(size_t)q*CO + col + 1] = mx1;
                    g_hmin[(size_t)q*CO + col]     = mn0;
                    g_hmin[(size_t)q*CO + col + 1] = mn1;
                }
            }
        }
    }

#pragma unroll
    for (int j = 0; j < 4; j++) {
        atomicAdd(&g_sum2  [colb + j*8],     st_s[j][0]);
        atomicAdd(&g_sumsq2[colb + j*8],     st_q[j][0]);
        atomicAdd(&g_sum2  [colb + j*8 + 1], st_s[j][1]);
        atomicAdd(&g_sumsq2[colb + j*8 + 1], st_q[j][1]);
    }
}

// ========== launch 4: BN2 finalize + pooled output ============================
__global__ __launch_bounds__(256)
void final_out_kernel(float* __restrict__ out,
                      const float* __restrict__ g2, const float* __restrict__ beta2)
{
    __shared__ float s_sc2[CO], s_sh2[CO];
    {
        int o = threadIdx.x;
        const float inv = 1.0f / (float)ROWS;
        float mean = g_sum2[o] * inv;
        float var  = g_sumsq2[o] * inv - mean*mean;
        float s = g2[o] * rsqrtf(var + 1e-5f);
        s_sc2[o] = s;
        s_sh2[o] = fmaf(-mean, s, beta2[o]);
    }
    __syncthreads();

    int t = blockIdx.x * 256 + threadIdx.x;
    int row = t >> 6, cg = t & 63;
    int c = cg * 4;
    float4 mx = *(const float4*)(g_hmax + (size_t)row*CO + c);
    float4 mn = *(const float4*)(g_hmin + (size_t)row*CO + c);
    float s0 = s_sc2[c+0], s1 = s_sc2[c+1], s2 = s_sc2[c+2], s3 = s_sc2[c+3];
    float h0 = s_sh2[c+0], h1 = s_sh2[c+1], h2 = s_sh2[c+2], h3 = s_sh2[c+3];
    float4 r;
    r.x = fmaxf(0.f, fmaf(s0 >= 0.f ? mx.x : mn.x, s0, h0));
    r.y = fmaxf(0.f, fmaf(s1 >= 0.f ? mx.y : mn.y, s1, h1));
    r.z = fmaxf(0.f, fmaf(s2 >= 0.f ? mx.z : mn.z, s2, h2));
    r.w = fmaxf(0.f, fmaf(s3 >= 0.f ? mx.w : mn.w, s3, h3));
    *(float4*)(out + NEWPOS_ELEMS + (size_t)row*CO + c) = r;
}

// ---------------- launch ----------------
extern "C" void kernel_launch(void* const* d_in, const int* in_sizes, int n_in,
                              void* d_out, int out_size)
{
    const float* pos    = (const float*)d_in[0];
    const float* points = (const float*)d_in[1];
    const int*   idx    = (const int*)  d_in[2];
    const float* W1     = (const float*)d_in[3];
    const float* b1     = (const float*)d_in[4];
    const float* g1     = (const float*)d_in[5];
    const float* beta1  = (const float*)d_in[6];
    const float* W2     = (const float*)d_in[7];
    const float* b2     = (const float*)d_in[8];
    const float* g2     = (const float*)d_in[9];
    const float* beta2  = (const float*)d_in[10];
    float* out = (float*)d_out;

    float *pP;
    cudaGetSymbolAddress((void**)&pP, g_P);

    cudaFuncSetAttribute(gemm2_mma_kernel,
                         cudaFuncAttributeMaxDynamicSharedMemorySize, SMEM_G2);

    // launch 0: kNN (+ stat zeroing)
    knn_kernel<<<QTOT/256, 256>>>(pos, idx, out);
    // launch 1: P = points @ W1p^T (+ W2 bf16 split)
    gemm_p_kernel<<<dim3((BB*NN)/128, CO/128), 256>>>(points, CC, W1, CI1, 3, pP, CC, W2);
    // launch 2: h1 assembly + BN1 stats
    assemble_h1_kernel<<<ROWS/64, 256>>>(pos, idx, W1, b1);
    // launch 3: GEMM2 warp-specialized + BN2 stats + pooled epilogue
    gemm2_mma_kernel<<<148, G2_THREADS, SMEM_G2>>>(b2, g1, beta1);
    // launch 4: BN2 finalize + output
    final_out_kernel<<<(QTOT*64)/256, 256>>>(out, g2, beta2);
}

// round 17
// speedup vs baseline: 1.5224x; 1.1921x over previous
#include <cuda_runtime.h>
#include <cuda_bf16.h>
#include <cuda_fp16.h>
#include <float.h>
#include <cstdint>

// Problem constants
#define BB   8
#define NN   8192
#define MM   4096
#define CC   128
#define KNN  16
#define CO   256
#define CI1  131
#define ROWS (BB*MM*KNN)  // 524288
#define QTOT (BB*MM)      // 32768
#define NEWPOS_ELEMS (QTOT*3)
#define MTILE2 (ROWS/256)       // 2048 M-tiles of 256 rows
#define NWORK2 (2*MTILE2)       // 4096 work items (M-tile x N-half)

// ---------------- static scratch (allocation-free rule) ----------------
__device__ float g_P [ (size_t)BB*NN*CO ];       // 64 MB   points @ W1p^T
__device__ float g_h1[ (size_t)ROWS*CO ];        // 512 MB  layer1 pre-activations
__device__ float g_hmax[ (size_t)QTOT*CO ];      // 32 MB
__device__ float g_hmin[ (size_t)QTOT*CO ];      // 32 MB
__device__ int   g_knn[ ROWS ];                  // 2 MB
__device__ __half g_Bhi[CO*CO];                  // W2 fp16 hi
__device__ __half g_Blo[CO*CO];                  // W2 fp16 lo (residual)
__device__ float g_sum1[CO], g_sumsq1[CO], g_sum2[CO], g_sumsq2[CO];

// ========== launch 0: kNN (+ stat zeroing) ====================================
__global__ __launch_bounds__(256)
void knn_kernel(const float* __restrict__ pos, const int* __restrict__ idx,
                float* __restrict__ out_newpos)
{
    if (blockIdx.x == 0 && threadIdx.x < CO) {
        int tt = threadIdx.x;
        g_sum1[tt] = 0.f;  g_sumsq1[tt] = 0.f;
        g_sum2[tt] = 0.f;  g_sumsq2[tt] = 0.f;
    }

    __shared__ float4 sp[2048];
    const int q = blockIdx.x * 256 + threadIdx.x;
    const int b = q >> 12;
    const float* pb = pos + (size_t)b * NN * 3;

    const int nq = idx[q];
    const float qx = pb[nq*3+0], qy = pb[nq*3+1], qz = pb[nq*3+2];
    out_newpos[q*3+0] = qx; out_newpos[q*3+1] = qy; out_newpos[q*3+2] = qz;
    const float qn = qx*qx + qy*qy + qz*qz;

    float dist[KNN]; int ind[KNN];
#pragma unroll
    for (int j = 0; j < KNN; j++) { dist[j] = FLT_MAX; ind[j] = 0x7fffffff; }

    for (int c0 = 0; c0 < NN; c0 += 2048) {
        __syncthreads();
        for (int i = threadIdx.x; i < 2048; i += 256) {
            float x = pb[(c0+i)*3+0], y = pb[(c0+i)*3+1], z = pb[(c0+i)*3+2];
            sp[i] = make_float4(x, y, z, x*x + y*y + z*z);
        }
        __syncthreads();
#pragma unroll 4
        for (int i = 0; i < 2048; i++) {
            float4 p = sp[i];
            float qp = qx*p.x + qy*p.y + qz*p.z;
            float d  = qn - 2.0f*qp + p.w;
            if (d < dist[0]) {
                const int nidx = c0 + i;
                bool prev = true;
#pragma unroll
                for (int j = 0; j < KNN-1; j++) {
                    bool nxt = d < dist[j+1];
                    float dj = nxt ? dist[j+1] : (prev ? d    : dist[j]);
                    int   ij = nxt ? ind[j+1]  : (prev ? nidx : ind[j]);
                    dist[j] = dj; ind[j] = ij;
                    prev = nxt;
                }
                if (prev) { dist[KNN-1] = d; ind[KNN-1] = nidx; }
            }
        }
    }
#pragma unroll
    for (int j = 0; j < KNN; j++) g_knn[q*KNN + j] = ind[j];
}

// ========== launch 1: gemm_p (+ fused W2 fp16 split) ==========================
__global__ __launch_bounds__(256, 2)
void gemm_p_kernel(const float* __restrict__ A, int lda,
                   const float* __restrict__ Bw, int ldb, int boff,
                   float* __restrict__ C, int Kdim,
                   const float* __restrict__ W2)
{
    if (blockIdx.y == 0 && blockIdx.x < 256) {
        int i = blockIdx.x * 256 + threadIdx.x;
        float v = W2[i];
        __half h = __float2half_rn(v);
        g_Bhi[i] = h;
        g_Blo[i] = __float2half_rn(v - __half2float(h));
    }

    const int BM = 128, BN = 128, BK = 16;
    __shared__ float As[BK][BM];
    __shared__ float Bs[BK][BN];

    const int t  = threadIdx.x;
    const int tx = t & 15, ty = t >> 4;
    const int rowBase = blockIdx.x * BM;
    const int colBase = blockIdx.y * BN;

    float acc[8][8];
#pragma unroll
    for (int i = 0; i < 8; i++)
#pragma unroll
        for (int j = 0; j < 8; j++) acc[i][j] = 0.f;

    for (int k0 = 0; k0 < Kdim; k0 += BK) {
#pragma unroll
        for (int l = 0; l < 2; l++) {
            int fid = t + l*256;
            int row = fid >> 2, c4 = (fid & 3) * 4;
            float4 v = *(const float4*)(A + (size_t)(rowBase + row)*lda + k0 + c4);
            As[c4+0][row] = v.x; As[c4+1][row] = v.y;
            As[c4+2][row] = v.z; As[c4+3][row] = v.w;
        }
#pragma unroll
        for (int l = 0; l < 8; l++) {
            int e = t + l*256;
            int c = e & 15, o = e >> 4;
            Bs[c][o] = Bw[(size_t)(colBase + o)*ldb + boff + k0 + c];
        }
        __syncthreads();
#pragma unroll
        for (int kk = 0; kk < BK; kk++) {
            float4 a0 = *(const float4*)&As[kk][ty*8];
            float4 a1 = *(const float4*)&As[kk][ty*8+4];
            float4 b0 = *(const float4*)&Bs[kk][tx*8];
            float4 b1 = *(const float4*)&Bs[kk][tx*8+4];
            float aR[8] = {a0.x,a0.y,a0.z,a0.w,a1.x,a1.y,a1.z,a1.w};
            float bR[8] = {b0.x,b0.y,b0.z,b0.w,b1.x,b1.y,b1.z,b1.w};
#pragma unroll
            for (int i = 0; i < 8; i++)
#pragma unroll
                for (int j = 0; j < 8; j++)
                    acc[i][j] = fmaf(aR[i], bR[j], acc[i][j]);
        }
        __syncthreads();
    }
#pragma unroll
    for (int i = 0; i < 8; i++) {
        int row = rowBase + ty*8 + i;
        float* cp = C + (size_t)row*CO + colBase + tx*8;
        *(float4*)cp       = make_float4(acc[i][0], acc[i][1], acc[i][2], acc[i][3]);
        *(float4*)(cp + 4) = make_float4(acc[i][4], acc[i][5], acc[i][6], acc[i][7]);
    }
}

// ========== launch 2: assemble h1 (+ BN1 stats) ===============================
__global__ __launch_bounds__(256)
void assemble_h1_kernel(const float* __restrict__ pos, const int* __restrict__ idx,
                        const float* __restrict__ W1, const float* __restrict__ b1)
{
    const int RPB = 64;
    __shared__ int   s_pb[RPB];
    __shared__ float s_r[RPB][3];
    const int base = blockIdx.x * RPB;
    const int t = threadIdx.x;
    if (t < RPB) {
        int r  = base + t;
        int b  = r >> 16;
        int m  = (r >> 4) & 4095;
        int nn = g_knn[r];
        const float* pb = pos + (size_t)b * NN * 3;
        int nq = idx[b*MM + m];
        s_r[t][0] = pb[nn*3+0] - pb[nq*3+0];
        s_r[t][1] = pb[nn*3+1] - pb[nq*3+1];
        s_r[t][2] = pb[nn*3+2] - pb[nq*3+2];
        s_pb[t]   = (b*NN + nn) * CO;
    }
    __syncthreads();
    const int o = t;
    const float w0 = W1[o*CI1+0], w1 = W1[o*CI1+1], w2 = W1[o*CI1+2], bb = b1[o];
    float ls = 0.f, lss = 0.f;
#pragma unroll 4
    for (int rr = 0; rr < RPB; rr++) {
        float v = g_P[(size_t)s_pb[rr] + o];
        v = v + bb + w0*s_r[rr][0] + w1*s_r[rr][1] + w2*s_r[rr][2];
        g_h1[(size_t)(base + rr)*CO + o] = v;
        ls += v; lss += v*v;
    }
    atomicAdd(&g_sum1[o], ls);
    atomicAdd(&g_sumsq1[o], lss);
}

// ========== launch 3: GEMM2, fp16 2-term, M-tile 256, 512 threads =============
// SMEM map:
//   [0,1024)        s_sc   [1024,2048) s_sh   [2048,3072) s_b2
//   [3072,+67584)   B hi (528 B/row x 128)
//   [70656,+67584)  B lo
//   [138240,+40960) A hi double-buffered: 2 x (256 rows x 80 B)
#define SM2_SC   0
#define SM2_SH   1024
#define SM2_B2   2048
#define SM2_BHI  3072
#define SM2_BLO  (SM2_BHI + 67584)
#define SM2_A    (SM2_BLO + 67584)     // 138240
#define SM2_ABUF 20480                 // one buffer = 256 rows x 80 B (hi only)
#define SMEM_G2  (SM2_A + 2*SM2_ABUF)  // 179200 bytes

__device__ __forceinline__ void mma16816h(float* c, const uint32_t* a,
                                          uint32_t b0, uint32_t b1) {
    asm volatile(
        "mma.sync.aligned.m16n8k16.row.col.f32.f16.f16.f32 "
        "{%0,%1,%2,%3}, {%4,%5,%6,%7}, {%8,%9}, {%0,%1,%2,%3};\n"
        : "+f"(c[0]), "+f"(c[1]), "+f"(c[2]), "+f"(c[3])
        : "r"(a[0]), "r"(a[1]), "r"(a[2]), "r"(a[3]), "r"(b0), "r"(b1));
}
__device__ __forceinline__ void ldsm_x4(uint32_t* r, uint32_t addr) {
    asm volatile("ldmatrix.sync.aligned.m8n8.x4.shared.b16 {%0,%1,%2,%3}, [%4];"
                 : "=r"(r[0]), "=r"(r[1]), "=r"(r[2]), "=r"(r[3]) : "r"(addr));
}
__device__ __forceinline__ uint32_t cvt_h2(float lo, float hi) {
    __half2 h = __floats2half2_rn(lo, hi);
    return *reinterpret_cast<uint32_t*>(&h);
}

__global__ __launch_bounds__(512, 1)
void gemm2_mma_kernel(const float* __restrict__ b2,
                      const float* __restrict__ g1, const float* __restrict__ beta1)
{
    extern __shared__ char smx[];
    float* s_sc = (float*)(smx + SM2_SC);
    float* s_sh = (float*)(smx + SM2_SH);
    float* s_b2 = (float*)(smx + SM2_B2);
    char*  sBhi = smx + SM2_BHI;
    char*  sBlo = smx + SM2_BLO;

    const int t    = threadIdx.x;
    const int lane = t & 31, wid = t >> 5;
    const int warp_m = wid & 3;         // 0..3 -> 64-row quarter (of 256)
    const int warp_n = wid >> 2;        // 0..3 -> 32-col slice
    const int nh   = blockIdx.x & 1;    // N-half (grid stride even -> fixed)

    const uint32_t smemBase = (uint32_t)__cvta_generic_to_shared(smx);

    // fused BN1 finalize (each CTA computes its own copy)
    if (t < 256) {
        const float inv = 1.0f / (float)ROWS;
        float mean = g_sum1[t] * inv;
        float var  = g_sumsq1[t] * inv - mean*mean;
        float s = g1[t] * rsqrtf(var + 1e-5f);
        s_sc[t] = s;
        s_sh[t] = fmaf(-mean, s, beta1[t]);
        s_b2[t] = b2[t];
    }

    // resident B half (hi/lo fp16): 128 rows x 256 ch, rows of 528 B
#pragma unroll
    for (int l = 0; l < 8; l++) {
        int e = t + l*512;
        int n = e >> 5, k8 = e & 31;
        size_t gsrc = ((size_t)(nh*128 + n))*CO + k8*8;
        *(uint4*)(sBhi + n*528 + k8*16) = *(const uint4*)(g_Bhi + gsrc);
        *(uint4*)(sBlo + n*528 + k8*16) = *(const uint4*)(g_Blo + gsrc);
    }

    float st_s[4][2], st_q[4][2];
    const int colb = nh*128 + warp_n*32 + 2*(lane & 3);
#pragma unroll
    for (int j = 0; j < 4; j++) {
        st_s[j][0] = st_s[j][1] = 0.f;
        st_q[j][0] = st_q[j][1] = 0.f;
    }

    // ldmatrix lane addressing
    const int aM = warp_m*64 + (lane & 7) + ((lane >> 3) & 1)*8;
    const uint32_t aLane = (uint32_t)(aM*80 + (lane >> 4)*16);
    const uint32_t aBase0 = smemBase + SM2_A + aLane;
    const uint32_t aBase1 = smemBase + SM2_A + SM2_ABUF + aLane;
    const int bN = warp_n*32 + (lane & 7) + (lane >> 4)*8;
    const uint32_t bKoff = ((lane >> 3) & 1)*16;
    const uint32_t bLaneHi = smemBase + SM2_BHI + bN*528 + bKoff;
    const uint32_t bLaneLo = smemBase + SM2_BLO + bN*528 + bKoff;

    const int qrow = t >> 1;            // loader row 0..255
    const int kq   = (t & 1) * 16;      // 16-channel half of 32-chunk

    __syncthreads();   // params + B resident visible

    for (int wi = blockIdx.x; wi < NWORK2; wi += gridDim.x) {
        const int mtile = wi >> 1;
        const size_t rowBase = (size_t)mtile * 256;

        float acc[4][4][4];
#pragma unroll
        for (int i = 0; i < 4; i++)
#pragma unroll
            for (int j = 0; j < 4; j++)
#pragma unroll
                for (int d = 0; d < 4; d++) acc[i][j][d] = 0.f;

        // prefetch chunk 0 (16 channels of this thread's row)
        float4 pf[4];
        {
            const float4* src = (const float4*)(g_h1 + (rowBase + qrow)*CO + kq);
            pf[0] = src[0]; pf[1] = src[1]; pf[2] = src[2]; pf[3] = src[3];
        }

        for (int c = 0; c < 8; c++) {
            const int buf = c & 1;
            // BN1+ReLU -> fp16, store 16 ch to A buf
            {
                char* aH = smx + SM2_A + buf*SM2_ABUF + qrow*80 + kq*2;
                const int cb = c*32 + kq;
                float x[16] = {pf[0].x, pf[0].y, pf[0].z, pf[0].w,
                               pf[1].x, pf[1].y, pf[1].z, pf[1].w,
                               pf[2].x, pf[2].y, pf[2].z, pf[2].w,
                               pf[3].x, pf[3].y, pf[3].z, pf[3].w};
#pragma unroll
                for (int v = 0; v < 16; v++)
                    x[v] = fmaxf(0.f, fmaf(x[v], s_sc[cb+v], s_sh[cb+v]));
                uint32_t uh[8];
#pragma unroll
                for (int p = 0; p < 8; p++) uh[p] = cvt_h2(x[2*p], x[2*p+1]);
                *(uint4*)(aH)      = make_uint4(uh[0], uh[1], uh[2], uh[3]);
                *(uint4*)(aH + 16) = make_uint4(uh[4], uh[5], uh[6], uh[7]);
            }
            // prefetch next chunk (overlaps mma below)
            if (c < 7) {
                const float4* src = (const float4*)(g_h1 + (rowBase + qrow)*CO
                                                    + (c+1)*32 + kq);
                pf[0] = src[0]; pf[1] = src[1]; pf[2] = src[2]; pf[3] = src[3];
            }
            __syncthreads();   // A chunk ready (double-buffered, 1 barrier/chunk)

            const uint32_t aAddr = (buf ? aBase1 : aBase0);
#pragma unroll
            for (int ks = 0; ks < 2; ks++) {
                uint32_t aHf[4][4], bHf[2][4], bLf[2][4];
#pragma unroll
                for (int i = 0; i < 4; i++)
                    ldsm_x4(aHf[i], aAddr + (uint32_t)(i*1280 + ks*32));
                const uint32_t cb2 = (uint32_t)(c*64 + ks*32);
#pragma unroll
                for (int jp = 0; jp < 2; jp++) {
                    ldsm_x4(bHf[jp], bLaneHi + (uint32_t)(jp*8448) + cb2);
                    ldsm_x4(bLf[jp], bLaneLo + (uint32_t)(jp*8448) + cb2);
                }
                // term 1: aH * bHi
#pragma unroll
                for (int j = 0; j < 4; j++)
#pragma unroll
                    for (int i = 0; i < 4; i++)
                        mma16816h(acc[i][j], aHf[i],
                                  bHf[j>>1][(j&1)*2], bHf[j>>1][(j&1)*2+1]);
                // term 2: aH * bLo
#pragma unroll
                for (int j = 0; j < 4; j++)
#pragma unroll
                    for (int i = 0; i < 4; i++)
                        mma16816h(acc[i][j], aHf[i],
                                  bLf[j>>1][(j&1)*2], bLf[j>>1][(j&1)*2+1]);
            }
        }

        // ---- fused epilogue: bias + stats + 16-row max/min pool ----
#pragma unroll
        for (int i = 0; i < 4; i++) {
            int q = mtile*16 + warp_m*4 + i;
#pragma unroll
            for (int j = 0; j < 4; j++) {
                float bb0 = s_b2[nh*128 + warp_n*32 + j*8 + 2*(lane & 3)];
                float bb1 = s_b2[nh*128 + warp_n*32 + j*8 + 2*(lane & 3) + 1];
                float v0 = acc[i][j][0] + bb0;
                float v1 = acc[i][j][1] + bb1;
                float v2 = acc[i][j][2] + bb0;
                float v3 = acc[i][j][3] + bb1;
                st_s[j][0] += v0 + v2;
                st_q[j][0] += v0*v0 + v2*v2;
                st_s[j][1] += v1 + v3;
                st_q[j][1] += v1*v1 + v3*v3;
                float mx0 = fmaxf(v0, v2), mn0 = fminf(v0, v2);
                float mx1 = fmaxf(v1, v3), mn1 = fminf(v1, v3);
#pragma unroll
                for (int s = 4; s <= 16; s <<= 1) {
                    mx0 = fmaxf(mx0, __shfl_xor_sync(0xffffffffu, mx0, s));
                    mn0 = fminf(mn0, __shfl_xor_sync(0xffffffffu, mn0, s));
                    mx1 = fmaxf(mx1, __shfl_xor_sync(0xffffffffu, mx1, s));
                    mn1 = fminf(mn1, __shfl_xor_sync(0xffffffffu, mn1, s));
                }
                if (lane < 4) {
                    int col = nh*128 + warp_n*32 + j*8 + 2*lane;
                    g_hmax[(size_t)q*CO + col]     = mx0;
                    g_hmax[(size_t)q*CO + col + 1] = mx1;
                    g_hmin[(size_t)q*CO + col]     = mn0;
                    g_hmin[(size_t)q*CO + col + 1] = mn1;
                }
            }
        }
    }

#pragma unroll
    for (int j = 0; j < 4; j++) {
        atomicAdd(&g_sum2  [colb + j*8],     st_s[j][0]);
        atomicAdd(&g_sumsq2[colb + j*8],     st_q[j][0]);
        atomicAdd(&g_sum2  [colb + j*8 + 1], st_s[j][1]);
        atomicAdd(&g_sumsq2[colb + j*8 + 1], st_q[j][1]);
    }
}

// ========== launch 4: BN2 finalize + pooled output ============================
__global__ __launch_bounds__(256)
void final_out_kernel(float* __restrict__ out,
                      const float* __restrict__ g2, const float* __restrict__ beta2)
{
    __shared__ float s_sc2[CO], s_sh2[CO];
    {
        int o = threadIdx.x;
        const float inv = 1.0f / (float)ROWS;
        float mean = g_sum2[o] * inv;
        float var  = g_sumsq2[o] * inv - mean*mean;
        float s = g2[o] * rsqrtf(var + 1e-5f);
        s_sc2[o] = s;
        s_sh2[o] = fmaf(-mean, s, beta2[o]);
    }
    __syncthreads();

    int t = blockIdx.x * 256 + threadIdx.x;
    int row = t >> 6, cg = t & 63;
    int c = cg * 4;
    float4 mx = *(const float4*)(g_hmax + (size_t)row*CO + c);
    float4 mn = *(const float4*)(g_hmin + (size_t)row*CO + c);
    float s0 = s_sc2[c+0], s1 = s_sc2[c+1], s2 = s_sc2[c+2], s3 = s_sc2[c+3];
    float h0 = s_sh2[c+0], h1 = s_sh2[c+1], h2 = s_sh2[c+2], h3 = s_sh2[c+3];
    float4 r;
    r.x = fmaxf(0.f, fmaf(s0 >= 0.f ? mx.x : mn.x, s0, h0));
    r.y = fmaxf(0.f, fmaf(s1 >= 0.f ? mx.y : mn.y, s1, h1));
    r.z = fmaxf(0.f, fmaf(s2 >= 0.f ? mx.z : mn.z, s2, h2));
    r.w = fmaxf(0.f, fmaf(s3 >= 0.f ? mx.w : mn.w, s3, h3));
    *(float4*)(out + NEWPOS_ELEMS + (size_t)row*CO + c) = r;
}

// ---------------- launch ----------------
extern "C" void kernel_launch(void* const* d_in, const int* in_sizes, int n_in,
                              void* d_out, int out_size)
{
    const float* pos    = (const float*)d_in[0];
    const float* points = (const float*)d_in[1];
    const int*   idx    = (const int*)  d_in[2];
    const float* W1     = (const float*)d_in[3];
    const float* b1     = (const float*)d_in[4];
    const float* g1     = (const float*)d_in[5];
    const float* beta1  = (const float*)d_in[6];
    const float* W2     = (const float*)d_in[7];
    const float* b2     = (const float*)d_in[8];
    const float* g2     = (const float*)d_in[9];
    const float* beta2  = (const float*)d_in[10];
    float* out = (float*)d_out;

    float *pP;
    cudaGetSymbolAddress((void**)&pP, g_P);

    cudaFuncSetAttribute(gemm2_mma_kernel,
                         cudaFuncAttributeMaxDynamicSharedMemorySize, SMEM_G2);

    // launch 0: kNN (+ stat zeroing)
    knn_kernel<<<QTOT/256, 256>>>(pos, idx, out);
    // launch 1: P = points @ W1p^T (+ W2 fp16 split)
    gemm_p_kernel<<<dim3((BB*NN)/128, CO/128), 256>>>(points, CC, W1, CI1, 3, pP, CC, W2);
    // launch 2: h1 assembly + BN1 stats
    assemble_h1_kernel<<<ROWS/64, 256>>>(pos, idx, W1, b1);
    // launch 3: GEMM2 fp16 2-term, M-tile 256 + BN2 stats + pooled epilogue
    gemm2_mma_kernel<<<148, 512, SMEM_G2>>>(b2, g1, beta1);
    // launch 4: BN2 finalize + output
    final_out_kernel<<<(QTOT*64)/256, 256>>>(out, g2, beta2);
}